// round 15
// baseline (speedup 1.0000x reference)
#include <cuda_runtime.h>
#include <cuda_bf16.h>

namespace {

typedef unsigned long long u64;
typedef unsigned int u32;

constexpr int IN_ = 16;
constexpr int H_ = 128;
constexpr int NT = 512;
constexpr float EPS = 1e-5f;
constexpr int ASTR = 68;          // bf16-plane row stride in u32 words (64 data + 4 pad; %32==4 -> conflict-free)
constexpr int APL = 64 * ASTR;    // hi->lo plane offset for 64-row planes (u32 words)
constexpr int PSTR = 36;          // P / V^T plane row stride in u32 words (32 data + 4 pad)
constexpr int PPL = 128 * PSTR;   // hi->lo plane offset for 128-row planes

// smem float offsets
constexpr int OFF_VB   = 0;        // 64x132 fp32 V / enc scratch
constexpr int OFF_HS   = 8448;     // 64x128 fp32 residual
constexpr int OFF_AHL  = 16640;    // activation bf16 hi/lo planes (2*APL u32)
constexpr int OFF_RA   = 25344;    // qpl (2*APL) -> vtpl (2*PPL)
constexpr int OFF_RB   = 34560;    // kpl (2*APL) -> ppl (2*PPL)
constexpr int OFF_RC   = 43776;    // B staging (8192 u32) / S (128x68) / ctx scratch (64x132)
constexpr int OFF_SVAL = 52480;    // 64
constexpr int SM_FLOATS = 52544;   // ~210KB

// B fragments packed for mma.m16n8k16: [mat 0..9][split 0..1][kt 0..7][nt 0..15][lane][2 u32]
constexpr int BW_U32 = 10 * 2 * 8 * 16 * 32 * 2;
__device__ __align__(16) u32 g_bw[BW_U32];
__device__ __align__(16) float2 g_wemb[8 * 128];

__device__ __forceinline__ u32 bfpair(float lo, float hi) {
    u32 r; asm("cvt.rn.bf16x2.f32 %0, %1, %2;" : "=r"(r) : "f"(hi), "f"(lo)); return r;
}
__device__ __forceinline__ float bfhi(float x) {
    return __bfloat162float(__float2bfloat16(x));
}

__global__ void pack_all(const float* __restrict__ Wemb, const float* __restrict__ We,
                         const float* __restrict__ Wq, const float* __restrict__ Wk,
                         const float* __restrict__ Wv) {
    int i = blockIdx.x * 256 + threadIdx.x;
    if (i < 1024) {
        int h = i & 127, m = i >> 7;
        g_wemb[i] = make_float2(Wemb[(2 * m) * H_ + h], Wemb[(2 * m + 1) * H_ + h]);
        return;
    }
    int j = i - 1024;
    if (j >= BW_U32) return;
    int reg  = j & 1;
    int lane = (j >> 1) & 31;
    int nt   = (j >> 6) & 15;
    int kt   = (j >> 10) & 7;
    int s    = (j >> 13) & 1;
    int m    = j >> 14;
    const float* src;
    if (m == 0) src = We;
    else { int r = m - 1, d = r / 3, w = r % 3;
           src = (w == 0 ? Wq : (w == 1 ? Wk : Wv)) + d * H_ * H_; }
    int k0 = kt * 16 + (lane & 3) * 2 + reg * 8;
    int n  = nt * 8 + (lane >> 2);
    float x0 = src[k0 * H_ + n], x1 = src[(k0 + 1) * H_ + n];
    if (s) { x0 -= bfhi(x0); x1 -= bfhi(x1); }
    g_bw[j] = bfpair(x0, x1);
}

// ---------------- scalar helpers (proven) ----------------
union F4 { float4 v; u64 u[2]; };
__device__ __forceinline__ void ffma2(u64& d, u64 a, u64 b) {
    asm("fma.rn.f32x2 %0, %1, %2, %0;" : "+l"(d) : "l"(a), "l"(b));
}
__device__ __forceinline__ float hsum2(u64 v) {
    float lo, hi; asm("mov.b64 {%0, %1}, %2;" : "=f"(lo), "=f"(hi) : "l"(v));
    return lo + hi;
}
__device__ __forceinline__ float warp_sum(float v) {
#pragma unroll
    for (int o = 16; o > 0; o >>= 1) v += __shfl_xor_sync(0xffffffffu, v, o);
    return v;
}
__device__ __forceinline__ float4 ln_warp(float4 x, float4 gm, float4 bt) {
    float s  = warp_sum(x.x + x.y + x.z + x.w);
    float ss = warp_sum(x.x * x.x + x.y * x.y + x.z * x.z + x.w * x.w);
    float mean = s * (1.f / H_);
    float inv  = rsqrtf(ss * (1.f / H_) - mean * mean + EPS);
    return make_float4(gm.x * (x.x - mean) * inv + bt.x, gm.y * (x.y - mean) * inv + bt.y,
                       gm.z * (x.z - mean) * inv + bt.z, gm.w * (x.w - mean) * inv + bt.w);
}

// write bf16 hi/lo planes of one row-slice (cols 4l..4l+3)
__device__ __forceinline__ void store_ahl(u32* __restrict__ ahl, int row, int l, float4 y) {
    u32 h0 = bfpair(y.x, y.y), h1 = bfpair(y.z, y.w);
    u32 l0 = bfpair(y.x - bfhi(y.x), y.y - bfhi(y.y));
    u32 l1 = bfpair(y.z - bfhi(y.z), y.w - bfhi(y.w));
    *reinterpret_cast<u64*>(ahl + row * ASTR + 2 * l)       = (u64)h0 | ((u64)h1 << 32);
    *reinterpret_cast<u64*>(ahl + APL + row * ASTR + 2 * l) = (u64)l0 | ((u64)l1 << 32);
}

#define HMMA(d, a0, a1, a2, a3, b0, b1) \
    asm volatile("mma.sync.aligned.m16n8k16.row.col.f32.bf16.bf16.f32 " \
        "{%0,%1,%2,%3},{%4,%5,%6,%7},{%8,%9},{%0,%1,%2,%3};" \
        : "+f"((d)[0]), "+f"((d)[1]), "+f"((d)[2]), "+f"((d)[3]) \
        : "r"(a0), "r"(a1), "r"(a2), "r"(a3), "r"(b0), "r"(b1))

// 64x128x128 GEMM with B staged through smem (SB, 8192 u32) to kill L2 redundancy.
// bsrc = 16384 u32 in global (hi 8192 | lo 8192).
__device__ __forceinline__ void gemm_staged(const u32* __restrict__ ahl,
                                            const u32* __restrict__ bsrc,
                                            u32* __restrict__ SB,
                                            int tid, int mt, int ng, int lane,
                                            float acc[4][4]) {
#pragma unroll
    for (int j = 0; j < 4; ++j)
#pragma unroll
        for (int r = 0; r < 4; ++r) acc[j][r] = 0.f;
    __syncthreads();                       // SB free (previous readers done)
    {
        const float4* s4 = reinterpret_cast<const float4*>(bsrc);
        float4* d4 = reinterpret_cast<float4*>(SB);
#pragma unroll
        for (int i = 0; i < 4; ++i) d4[tid + i * 512] = s4[tid + i * 512];
    }
    __syncthreads();
    const u64* B = reinterpret_cast<const u64*>(SB);
    const int rb = (mt * 16 + (lane >> 2)) * ASTR;
#pragma unroll
    for (int kt = 0; kt < 8; ++kt) {
        const int ca = kt * 8 + (lane & 3);
        u32 ah0 = ahl[rb + ca],             ah1 = ahl[rb + 8 * ASTR + ca];
        u32 ah2 = ahl[rb + ca + 4],         ah3 = ahl[rb + 8 * ASTR + ca + 4];
        u32 al0 = ahl[APL + rb + ca],       al1 = ahl[APL + rb + 8 * ASTR + ca];
        u32 al2 = ahl[APL + rb + ca + 4],   al3 = ahl[APL + rb + 8 * ASTR + ca + 4];
#pragma unroll
        for (int j = 0; j < 4; ++j) {
            const int nt = ng * 4 + j;
            u64 bh = B[(kt * 16 + nt) * 32 + lane];
            u32 bh0 = (u32)bh, bh1 = (u32)(bh >> 32);
            HMMA(acc[j], ah0, ah1, ah2, ah3, bh0, bh1);
            HMMA(acc[j], al0, al1, al2, al3, bh0, bh1);
        }
    }
    __syncthreads();                       // hi reads done
    {
        const float4* s4 = reinterpret_cast<const float4*>(bsrc) + 2048;
        float4* d4 = reinterpret_cast<float4*>(SB);
#pragma unroll
        for (int i = 0; i < 4; ++i) d4[tid + i * 512] = s4[tid + i * 512];
    }
    __syncthreads();
#pragma unroll
    for (int kt = 0; kt < 8; ++kt) {
        const int ca = kt * 8 + (lane & 3);
        u32 ah0 = ahl[rb + ca],           ah1 = ahl[rb + 8 * ASTR + ca];
        u32 ah2 = ahl[rb + ca + 4],       ah3 = ahl[rb + 8 * ASTR + ca + 4];
#pragma unroll
        for (int j = 0; j < 4; ++j) {
            const int nt = ng * 4 + j;
            u64 bl = B[(kt * 16 + nt) * 32 + lane];
            u32 bl0 = (u32)bl, bl1 = (u32)(bl >> 32);
            HMMA(acc[j], ah0, ah1, ah2, ah3, bl0, bl1);
        }
    }
}

// D tile (+bias) -> pitched fp32 buffer (132-float rows) (proven)
__device__ __forceinline__ void store_tile(float* __restrict__ buf,
                                           const float* __restrict__ biasg,
                                           int mt, int ng, int lane, float acc[4][4]) {
    const int g = lane >> 2, q = lane & 3;
#pragma unroll
    for (int j = 0; j < 4; ++j) {
        const int c = ng * 32 + j * 8 + q * 2;
        float2 bv = *reinterpret_cast<const float2*>(biasg + c);
        const int r = mt * 16 + g;
        *reinterpret_cast<float2*>(buf + r * 132 + c) =
            make_float2(acc[j][0] + bv.x, acc[j][1] + bv.y);
        *reinterpret_cast<float2*>(buf + (r + 8) * 132 + c) =
            make_float2(acc[j][2] + bv.x, acc[j][3] + bv.y);
    }
}

// D tile (+bias) -> bf16 hi/lo planes (row-major, stride ASTR) for Q/K (proven)
__device__ __forceinline__ void store_planes(u32* __restrict__ pl,
                                             const float* __restrict__ biasg,
                                             int mt, int ng, int lane, float acc[4][4]) {
    const int g = lane >> 2, t = lane & 3;
    const int r = mt * 16 + g;
#pragma unroll
    for (int j = 0; j < 4; ++j) {
        const int c = ng * 32 + j * 8 + t * 2;
        float2 bv = *reinterpret_cast<const float2*>(biasg + c);
        const int w = ng * 16 + j * 4 + t;
        float x0 = acc[j][0] + bv.x, x1 = acc[j][1] + bv.y;
        float x2 = acc[j][2] + bv.x, x3 = acc[j][3] + bv.y;
        pl[r * ASTR + w]             = bfpair(x0, x1);
        pl[(r + 8) * ASTR + w]       = bfpair(x2, x3);
        pl[APL + r * ASTR + w]       = bfpair(x0 - bfhi(x0), x1 - bfhi(x1));
        pl[APL + (r + 8) * ASTR + w] = bfpair(x2 - bfhi(x2), x3 - bfhi(x3));
    }
}

// scores S[head*64+q][k] = Q_head . K_head^T (proven)
__device__ __forceinline__ void attn_scores(const u32* __restrict__ qpl,
                                            const u32* __restrict__ kpl,
                                            float* __restrict__ S,
                                            int wid, int lane) {
    const int head = wid >> 3, mt = (wid >> 1) & 3, nh = wid & 1;
    const int g = lane >> 2, t = lane & 3;
    float acc[4][4] = {};
    const int rb = (mt * 16 + g) * ASTR + head * 32;
#pragma unroll
    for (int kt = 0; kt < 4; ++kt) {
        const int ca = rb + kt * 8 + t;
        u32 ah0 = qpl[ca],           ah1 = qpl[8 * ASTR + ca];
        u32 ah2 = qpl[ca + 4],       ah3 = qpl[8 * ASTR + ca + 4];
        u32 al0 = qpl[APL + ca],     al1 = qpl[APL + 8 * ASTR + ca];
        u32 al2 = qpl[APL + ca + 4], al3 = qpl[APL + 8 * ASTR + ca + 4];
#pragma unroll
        for (int j = 0; j < 4; ++j) {
            const int kw = (nh * 32 + j * 8 + g) * ASTR + head * 32 + kt * 8 + t;
            u32 bh0 = kpl[kw],       bh1 = kpl[kw + 4];
            u32 bl0 = kpl[APL + kw], bl1 = kpl[APL + kw + 4];
            HMMA(acc[j], ah0, ah1, ah2, ah3, bh0, bh1);
            HMMA(acc[j], al0, al1, al2, al3, bh0, bh1);
            HMMA(acc[j], ah0, ah1, ah2, ah3, bl0, bl1);
        }
    }
    const int r = head * 64 + mt * 16 + g;
#pragma unroll
    for (int j = 0; j < 4; ++j) {
        const int c = nh * 32 + j * 8 + 2 * t;
        *reinterpret_cast<float2*>(S + r * 68 + c)       = make_float2(acc[j][0], acc[j][1]);
        *reinterpret_cast<float2*>(S + (r + 8) * 68 + c) = make_float2(acc[j][2], acc[j][3]);
    }
}

// softmax rows of S (scale + mask) -> P bf16 hi/lo planes (proven)
__device__ __forceinline__ void softmax_p(const float* __restrict__ S,
                                          u32* __restrict__ ppl,
                                          const float* __restrict__ sval, int tid) {
    const int row = tid >> 2, quad = tid & 3;
    const float vq = sval[row & 63];
    const float* srow = S + row * 68 + quad * 16;
    const float* svk  = sval + quad * 16;
    float s[16];
    float mx = -3.4e38f;
#pragma unroll
    for (int i = 0; i < 16; ++i) {
        s[i] = srow[i] * 0.125f + (1.f - vq * svk[i]) * -10000.f;
        mx = fmaxf(mx, s[i]);
    }
    mx = fmaxf(mx, __shfl_xor_sync(0xffffffffu, mx, 1));
    mx = fmaxf(mx, __shfl_xor_sync(0xffffffffu, mx, 2));
    float sum = 0.f;
#pragma unroll
    for (int i = 0; i < 16; ++i) { s[i] = __expf(s[i] - mx); sum += s[i]; }
    sum += __shfl_xor_sync(0xffffffffu, sum, 1);
    sum += __shfl_xor_sync(0xffffffffu, sum, 2);
    const float inv = 1.f / sum;
    u32* prow = ppl + row * PSTR + quad * 8;
#pragma unroll
    for (int ii = 0; ii < 8; ++ii) {
        float p0 = s[2 * ii] * inv, p1 = s[2 * ii + 1] * inv;
        prow[ii]       = bfpair(p0, p1);
        prow[PPL + ii] = bfpair(p0 - bfhi(p0), p1 - bfhi(p1));
    }
}

// vb fp32 (token-major) -> V^T bf16 hi/lo planes (proven)
__device__ __forceinline__ void v_transpose(const float* __restrict__ vb,
                                            u32* __restrict__ vtpl, int tid) {
#pragma unroll
    for (int i = 0; i < 8; ++i) {
        const int idx = i * 512 + tid;
        const int h = idx & 127, w = idx >> 7;
        float v0 = vb[(2 * w) * 132 + h];
        float v1 = vb[(2 * w + 1) * 132 + h];
        vtpl[h * PSTR + w]       = bfpair(v0, v1);
        vtpl[PPL + h * PSTR + w] = bfpair(v0 - bfhi(v0), v1 - bfhi(v1));
    }
}

// ctx = P @ V -> fp32 scratch (pitch 132) (proven)
__device__ __forceinline__ void attn_ctx(const u32* __restrict__ ppl,
                                         const u32* __restrict__ vtpl,
                                         float* __restrict__ ctx,
                                         int wid, int lane) {
    const int mt = wid & 3, ng = wid >> 2;
    const int head = ng >> 1;
    const int g = lane >> 2, t = lane & 3;
    float acc[4][4] = {};
    const int rb = (head * 64 + mt * 16 + g) * PSTR;
#pragma unroll
    for (int kt = 0; kt < 4; ++kt) {
        const int ca = rb + kt * 8 + t;
        u32 ah0 = ppl[ca],           ah1 = ppl[8 * PSTR + ca];
        u32 ah2 = ppl[ca + 4],       ah3 = ppl[8 * PSTR + ca + 4];
        u32 al0 = ppl[PPL + ca],     al1 = ppl[PPL + 8 * PSTR + ca];
        u32 al2 = ppl[PPL + ca + 4], al3 = ppl[PPL + 8 * PSTR + ca + 4];
#pragma unroll
        for (int j = 0; j < 4; ++j) {
            const int vw = (ng * 32 + j * 8 + g) * PSTR + kt * 8 + t;
            u32 bh0 = vtpl[vw],       bh1 = vtpl[vw + 4];
            u32 bl0 = vtpl[PPL + vw], bl1 = vtpl[PPL + vw + 4];
            HMMA(acc[j], ah0, ah1, ah2, ah3, bh0, bh1);
            HMMA(acc[j], al0, al1, al2, al3, bh0, bh1);
            HMMA(acc[j], ah0, ah1, ah2, ah3, bl0, bl1);
        }
    }
    const int r = mt * 16 + g;
#pragma unroll
    for (int j = 0; j < 4; ++j) {
        const int c = ng * 32 + j * 8 + 2 * t;
        *reinterpret_cast<float2*>(ctx + r * 132 + c)       = make_float2(acc[j][0], acc[j][1]);
        *reinterpret_cast<float2*>(ctx + (r + 8) * 132 + c) = make_float2(acc[j][2], acc[j][3]);
    }
}

// K=16 emb gemm, 4 tokens, x from global (proven)
__device__ __forceinline__ void gemm16(const float4* __restrict__ wp4,
                                       const float4* __restrict__ xg4,
                                       int t0, int l, float4 bias, float4 res[4]) {
    u64 acc[4][4] = {};
#pragma unroll
    for (int kb = 0; kb < 4; ++kb) {
        const float4* w0 = wp4 + (2 * kb) * 64 + 2 * l;
        const float4* w1 = wp4 + (2 * kb + 1) * 64 + 2 * l;
        F4 A0, A1, B0, B1;
        A0.v = w0[0]; A1.v = w0[1]; B0.v = w1[0]; B1.v = w1[1];
#pragma unroll
        for (int t = 0; t < 4; ++t) {
            F4 x; x.v = xg4[(t0 + t) * 4 + kb];
            ffma2(acc[t][0], x.u[0], A0.u[0]); ffma2(acc[t][0], x.u[1], B0.u[0]);
            ffma2(acc[t][1], x.u[0], A0.u[1]); ffma2(acc[t][1], x.u[1], B0.u[1]);
            ffma2(acc[t][2], x.u[0], A1.u[0]); ffma2(acc[t][2], x.u[1], B1.u[0]);
            ffma2(acc[t][3], x.u[0], A1.u[1]); ffma2(acc[t][3], x.u[1], B1.u[1]);
        }
    }
#pragma unroll
    for (int t = 0; t < 4; ++t)
        res[t] = make_float4(hsum2(acc[t][0]) + bias.x, hsum2(acc[t][1]) + bias.y,
                             hsum2(acc[t][2]) + bias.z, hsum2(acc[t][3]) + bias.w);
}

// ================= main fused kernel: 1 sequence per CTA =================
__global__ void __launch_bounds__(NT, 1) fused_lane_encoder(
    const float* __restrict__ feat, const float* __restrict__ masks,
    const float* __restrict__ b_emb, const float* __restrict__ g_emb,
    const float* __restrict__ beta_emb,
    const float* __restrict__ b_enc, const float* __restrict__ g_enc,
    const float* __restrict__ beta_enc,
    const float* __restrict__ bq, const float* __restrict__ bk,
    const float* __restrict__ bv,
    const float* __restrict__ ln_g, const float* __restrict__ ln_b,
    float* __restrict__ out)
{
    extern __shared__ float smem[];
    float* const vb   = smem + OFF_VB;
    float* const hs   = smem + OFF_HS;
    u32*   const ahl  = reinterpret_cast<u32*>(smem + OFF_AHL);
    u32*   const RA   = reinterpret_cast<u32*>(smem + OFF_RA);
    u32*   const RB   = reinterpret_cast<u32*>(smem + OFF_RB);
    float* const RC   = smem + OFF_RC;
    u32*   const SB   = reinterpret_cast<u32*>(RC);
    float* const sval = smem + OFF_SVAL;

    float4* const hs4 = reinterpret_cast<float4*>(hs);

    const int tid  = threadIdx.x;
    const int lane = tid & 31;
    const int wid  = tid >> 5;       // 0..15
    const int mt   = wid & 3;
    const int ng   = wid >> 2;
    const int blk  = blockIdx.x;

    if (tid < 64) sval[tid] = 1.0f - masks[(size_t)blk * 64 + tid];

    // ---- Phase 1: emb = relu(LN(feat @ W_emb + b)); warp owns 4 tokens ----
    {
        const float4* fg4 = reinterpret_cast<const float4*>(feat + (size_t)blk * 64 * IN_);
        const float4* we4 = reinterpret_cast<const float4*>(g_wemb);
        float4 bias = *reinterpret_cast<const float4*>(b_emb + 4 * lane);
        float4 gm   = *reinterpret_cast<const float4*>(g_emb + 4 * lane);
        float4 bt   = *reinterpret_cast<const float4*>(beta_emb + 4 * lane);
        int t0 = wid * 4;
        float4 r[4];
        gemm16(we4, fg4, t0, lane, bias, r);
#pragma unroll
        for (int t = 0; t < 4; ++t) {
            float4 y = ln_warp(r[t], gm, bt);
            y = make_float4(fmaxf(y.x, 0.f), fmaxf(y.y, 0.f), fmaxf(y.z, 0.f), fmaxf(y.w, 0.f));
            hs4[(t0 + t) * 32 + lane] = y;
            store_ahl(ahl, t0 + t, lane, y);
        }
    }
    __syncthreads();

    // ---- Phase 2: enc GEMM (staged B) -> vb, then LN/relu -> hs + ahl ----
    {
        float acc[4][4];
        gemm_staged(ahl, g_bw, SB, tid, mt, ng, lane, acc);
        store_tile(vb, b_enc, mt, ng, lane, acc);
    }
    __syncthreads();
    {
        const float4* vb4c = reinterpret_cast<const float4*>(vb);
        float4 gm = *reinterpret_cast<const float4*>(g_enc + 4 * lane);
        float4 bt = *reinterpret_cast<const float4*>(beta_enc + 4 * lane);
        int t0 = wid * 4;
#pragma unroll
        for (int t = 0; t < 4; ++t) {
            float4 x = vb4c[(t0 + t) * 33 + lane];
            float4 y = ln_warp(x, gm, bt);
            y = make_float4(fmaxf(y.x, 0.f), fmaxf(y.y, 0.f), fmaxf(y.z, 0.f), fmaxf(y.w, 0.f));
            hs4[(t0 + t) * 32 + lane] = y;
            store_ahl(ahl, t0 + t, lane, y);
        }
    }
    __syncthreads();

    // ---- Phase 3: transformer layers (fully HMMA, staged B) ----
    for (int d = 0; d < 3; ++d) {
        {
            float acc[4][4];
            gemm_staged(ahl, g_bw + (size_t)(1 + 3 * d) * 16384, SB, tid, mt, ng, lane, acc);
            store_planes(RA, bq + d * H_, mt, ng, lane, acc);       // Q planes
            gemm_staged(ahl, g_bw + (size_t)(2 + 3 * d) * 16384, SB, tid, mt, ng, lane, acc);
            store_planes(RB, bk + d * H_, mt, ng, lane, acc);       // K planes
            gemm_staged(ahl, g_bw + (size_t)(3 + 3 * d) * 16384, SB, tid, mt, ng, lane, acc);
            store_tile(vb, bv + d * H_, mt, ng, lane, acc);         // V fp32
        }
        __syncthreads();

        attn_scores(RA, RB, RC, wid, lane);                         // S = Q.K^T (over SB)
        __syncthreads();

        softmax_p(RC, RB, sval, tid);                               // P planes (over kpl)
        v_transpose(vb, RA, tid);                                   // V^T planes (over qpl)
        __syncthreads();

        attn_ctx(RB, RA, RC, wid, lane);                            // ctx (over S)
        __syncthreads();

        {   // residual + LN epilogue (warp-local)
            const float4* rc4 = reinterpret_cast<const float4*>(RC);
            float4 gm = *reinterpret_cast<const float4*>(ln_g + d * H_ + 4 * lane);
            float4 bt = *reinterpret_cast<const float4*>(ln_b + d * H_ + 4 * lane);
            int t0 = wid * 4;
#pragma unroll
            for (int t = 0; t < 4; ++t) {
                int row = t0 + t;
                float4 cv = rc4[row * 33 + lane];
                float4 hv = hs4[row * 32 + lane];
                float4 x = make_float4(fmaxf(cv.x, 0.f) + hv.x, fmaxf(cv.y, 0.f) + hv.y,
                                       fmaxf(cv.z, 0.f) + hv.z, fmaxf(cv.w, 0.f) + hv.w);
                float4 y = ln_warp(x, gm, bt);
                hs4[row * 32 + lane] = y;
                if (d < 2) store_ahl(ahl, row, lane, y);
            }
        }
        __syncthreads();
    }

    // ---- Phase 4: max over T (scratch = RC) ----
    {
        const int part = tid >> 7;
        const int hh   = tid & 127;
        float m = -3.4e38f;
#pragma unroll
        for (int t = 0; t < 16; ++t)
            m = fmaxf(m, hs[(part * 16 + t) * H_ + hh]);
        RC[part * H_ + hh] = m;
    }
    __syncthreads();
    if (tid < H_)
        out[(size_t)blk * H_ + tid] = fmaxf(fmaxf(RC[tid], RC[H_ + tid]),
                                            fmaxf(RC[2 * H_ + tid], RC[3 * H_ + tid]));
}

} // namespace

extern "C" void kernel_launch(void* const* d_in, const int* in_sizes, int n_in,
                              void* d_out, int out_size) {
    const float* feat     = (const float*)d_in[0];
    const float* masks    = (const float*)d_in[1];
    const float* W_emb    = (const float*)d_in[2];
    const float* b_emb    = (const float*)d_in[3];
    const float* g_emb    = (const float*)d_in[4];
    const float* beta_emb = (const float*)d_in[5];
    const float* W_enc    = (const float*)d_in[6];
    const float* b_enc    = (const float*)d_in[7];
    const float* g_enc    = (const float*)d_in[8];
    const float* beta_enc = (const float*)d_in[9];
    const float* Wq       = (const float*)d_in[10];
    const float* bq       = (const float*)d_in[11];
    const float* Wk       = (const float*)d_in[12];
    const float* bk       = (const float*)d_in[13];
    const float* Wv       = (const float*)d_in[14];
    const float* bv       = (const float*)d_in[15];
    const float* ln_g     = (const float*)d_in[16];
    const float* ln_b     = (const float*)d_in[17];
    float* out = (float*)d_out;

    int nseq = in_sizes[0] / (64 * IN_);   // 4096
    pack_all<<<(1024 + BW_U32 + 255) / 256, 256>>>(W_emb, W_enc, Wq, Wk, Wv);

    size_t smem = (size_t)SM_FLOATS * 4;   // ~210KB
    cudaFuncSetAttribute(fused_lane_encoder,
                         cudaFuncAttributeMaxDynamicSharedMemorySize, (int)smem);
    fused_lane_encoder<<<nseq, NT, smem>>>(
        feat, masks, b_emb, g_emb, beta_emb, b_enc, g_enc, beta_enc,
        bq, bk, bv, ln_g, ln_b, out);
}

// round 16
// speedup vs baseline: 1.2169x; 1.2169x over previous
#include <cuda_runtime.h>
#include <cuda_bf16.h>

namespace {

typedef unsigned long long u64;
typedef unsigned int u32;

constexpr int IN_ = 16;
constexpr int H_ = 128;
constexpr int NT = 512;
constexpr float EPS = 1e-5f;
constexpr int ASTR = 68;          // bf16-plane row stride in u32 words (64 data + 4 pad; %32==4 -> conflict-free)
constexpr int APL = 64 * ASTR;    // hi->lo plane offset for 64-row planes (u32 words)
constexpr int PSTR = 36;          // P / V^T plane row stride in u32 words (32 data + 4 pad)
constexpr int PPL = 128 * PSTR;   // hi->lo plane offset for 128-row planes

// smem float offsets
constexpr int OFF_HS   = 0;        // 64x128 fp32 residual
constexpr int OFF_AHL  = 8192;     // activation bf16 hi/lo planes (2*APL u32 = 8704)
constexpr int OFF_VT   = 16896;    // V^T planes (2*PPL = 9216)
constexpr int OFF_QP   = 26112;    // Q planes (2*APL = 8704)
constexpr int OFF_KP   = 34816;    // K planes -> P planes (max(2*APL, 2*PPL) = 9216)
constexpr int OFF_RC   = 44032;    // enc scratch / ctx scratch (64x132 = 8448)
constexpr int OFF_SVAL = 52480;    // 64
constexpr int OFF_PMX  = 52544;    // 2 x 128 row-max exchange
constexpr int OFF_PSM  = 52800;    // 2 x 128 row-sum exchange
constexpr int SM_FLOATS = 53056;   // ~212KB

// B fragments packed for mma.m16n8k16: [mat 0..9][split 0..1][kt 0..7][nt 0..15][lane][2 u32]
constexpr int BW_U32 = 10 * 2 * 8 * 16 * 32 * 2;
__device__ __align__(16) u32 g_bw[BW_U32];
__device__ __align__(16) float2 g_wemb[8 * 128];

__device__ __forceinline__ u32 bfpair(float lo, float hi) {
    u32 r; asm("cvt.rn.bf16x2.f32 %0, %1, %2;" : "=r"(r) : "f"(hi), "f"(lo)); return r;
}
__device__ __forceinline__ float bfhi(float x) {
    return __bfloat162float(__float2bfloat16(x));
}

__global__ void pack_all(const float* __restrict__ Wemb, const float* __restrict__ We,
                         const float* __restrict__ Wq, const float* __restrict__ Wk,
                         const float* __restrict__ Wv) {
    int i = blockIdx.x * 256 + threadIdx.x;
    if (i < 1024) {
        int h = i & 127, m = i >> 7;
        g_wemb[i] = make_float2(Wemb[(2 * m) * H_ + h], Wemb[(2 * m + 1) * H_ + h]);
        return;
    }
    int j = i - 1024;
    if (j >= BW_U32) return;
    int reg  = j & 1;
    int lane = (j >> 1) & 31;
    int nt   = (j >> 6) & 15;
    int kt   = (j >> 10) & 7;
    int s    = (j >> 13) & 1;
    int m    = j >> 14;
    const float* src;
    if (m == 0) src = We;
    else { int r = m - 1, d = r / 3, w = r % 3;
           src = (w == 0 ? Wq : (w == 1 ? Wk : Wv)) + d * H_ * H_; }
    int k0 = kt * 16 + (lane & 3) * 2 + reg * 8;
    int n  = nt * 8 + (lane >> 2);
    float x0 = src[k0 * H_ + n], x1 = src[(k0 + 1) * H_ + n];
    if (s) { x0 -= bfhi(x0); x1 -= bfhi(x1); }
    g_bw[j] = bfpair(x0, x1);
}

// ---------------- scalar helpers (proven) ----------------
union F4 { float4 v; u64 u[2]; };
__device__ __forceinline__ void ffma2(u64& d, u64 a, u64 b) {
    asm("fma.rn.f32x2 %0, %1, %2, %0;" : "+l"(d) : "l"(a), "l"(b));
}
__device__ __forceinline__ float hsum2(u64 v) {
    float lo, hi; asm("mov.b64 {%0, %1}, %2;" : "=f"(lo), "=f"(hi) : "l"(v));
    return lo + hi;
}
__device__ __forceinline__ float warp_sum(float v) {
#pragma unroll
    for (int o = 16; o > 0; o >>= 1) v += __shfl_xor_sync(0xffffffffu, v, o);
    return v;
}
__device__ __forceinline__ float4 ln_warp(float4 x, float4 gm, float4 bt) {
    float s  = warp_sum(x.x + x.y + x.z + x.w);
    float ss = warp_sum(x.x * x.x + x.y * x.y + x.z * x.z + x.w * x.w);
    float mean = s * (1.f / H_);
    float inv  = rsqrtf(ss * (1.f / H_) - mean * mean + EPS);
    return make_float4(gm.x * (x.x - mean) * inv + bt.x, gm.y * (x.y - mean) * inv + bt.y,
                       gm.z * (x.z - mean) * inv + bt.z, gm.w * (x.w - mean) * inv + bt.w);
}

// write bf16 hi/lo planes of one row-slice (cols 4l..4l+3)
__device__ __forceinline__ void store_ahl(u32* __restrict__ ahl, int row, int l, float4 y) {
    u32 h0 = bfpair(y.x, y.y), h1 = bfpair(y.z, y.w);
    u32 l0 = bfpair(y.x - bfhi(y.x), y.y - bfhi(y.y));
    u32 l1 = bfpair(y.z - bfhi(y.z), y.w - bfhi(y.w));
    *reinterpret_cast<u64*>(ahl + row * ASTR + 2 * l)       = (u64)h0 | ((u64)h1 << 32);
    *reinterpret_cast<u64*>(ahl + APL + row * ASTR + 2 * l) = (u64)l0 | ((u64)l1 << 32);
}

#define HMMA(d, a0, a1, a2, a3, b0, b1) \
    asm volatile("mma.sync.aligned.m16n8k16.row.col.f32.bf16.bf16.f32 " \
        "{%0,%1,%2,%3},{%4,%5,%6,%7},{%8,%9},{%0,%1,%2,%3};" \
        : "+f"((d)[0]), "+f"((d)[1]), "+f"((d)[2]), "+f"((d)[3]) \
        : "r"(a0), "r"(a1), "r"(a2), "r"(a3), "r"(b0), "r"(b1))

// one 64x128x128 GEMM tile-slice, B direct from L2 (R14 proven)
__device__ __forceinline__ void gemm_mma(const u32* __restrict__ ahl,
                                         const u64* __restrict__ bw,
                                         int mt, int ng, int lane, float acc[4][4]) {
#pragma unroll
    for (int j = 0; j < 4; ++j)
#pragma unroll
        for (int r = 0; r < 4; ++r) acc[j][r] = 0.f;
    const int rb = (mt * 16 + (lane >> 2)) * ASTR;
#pragma unroll
    for (int kt = 0; kt < 8; ++kt) {
        const int ca = kt * 8 + (lane & 3);
        u32 ah0 = ahl[rb + ca],             ah1 = ahl[rb + 8 * ASTR + ca];
        u32 ah2 = ahl[rb + ca + 4],         ah3 = ahl[rb + 8 * ASTR + ca + 4];
        u32 al0 = ahl[APL + rb + ca],       al1 = ahl[APL + rb + 8 * ASTR + ca];
        u32 al2 = ahl[APL + rb + ca + 4],   al3 = ahl[APL + rb + 8 * ASTR + ca + 4];
#pragma unroll
        for (int j = 0; j < 4; ++j) {
            const int nt = ng * 4 + j;
            u64 bh = bw[(kt * 16 + nt) * 32 + lane];
            u64 bl = bw[4096 + (kt * 16 + nt) * 32 + lane];
            u32 bh0 = (u32)bh, bh1 = (u32)(bh >> 32);
            u32 bl0 = (u32)bl, bl1 = (u32)(bl >> 32);
            HMMA(acc[j], ah0, ah1, ah2, ah3, bh0, bh1);
            HMMA(acc[j], al0, al1, al2, al3, bh0, bh1);
            HMMA(acc[j], ah0, ah1, ah2, ah3, bl0, bl1);
        }
    }
}

// D tile (+bias) -> pitched fp32 buffer (132-float rows) (proven)
__device__ __forceinline__ void store_tile(float* __restrict__ buf,
                                           const float* __restrict__ biasg,
                                           int mt, int ng, int lane, float acc[4][4]) {
    const int g = lane >> 2, q = lane & 3;
#pragma unroll
    for (int j = 0; j < 4; ++j) {
        const int c = ng * 32 + j * 8 + q * 2;
        float2 bv = *reinterpret_cast<const float2*>(biasg + c);
        const int r = mt * 16 + g;
        *reinterpret_cast<float2*>(buf + r * 132 + c) =
            make_float2(acc[j][0] + bv.x, acc[j][1] + bv.y);
        *reinterpret_cast<float2*>(buf + (r + 8) * 132 + c) =
            make_float2(acc[j][2] + bv.x, acc[j][3] + bv.y);
    }
}

// D tile (+bias) -> bf16 hi/lo planes (row-major, stride ASTR) for Q/K (proven)
__device__ __forceinline__ void store_planes(u32* __restrict__ pl,
                                             const float* __restrict__ biasg,
                                             int mt, int ng, int lane, float acc[4][4]) {
    const int g = lane >> 2, t = lane & 3;
    const int r = mt * 16 + g;
#pragma unroll
    for (int j = 0; j < 4; ++j) {
        const int c = ng * 32 + j * 8 + t * 2;
        float2 bv = *reinterpret_cast<const float2*>(biasg + c);
        const int w = ng * 16 + j * 4 + t;
        float x0 = acc[j][0] + bv.x, x1 = acc[j][1] + bv.y;
        float x2 = acc[j][2] + bv.x, x3 = acc[j][3] + bv.y;
        pl[r * ASTR + w]             = bfpair(x0, x1);
        pl[(r + 8) * ASTR + w]       = bfpair(x2, x3);
        pl[APL + r * ASTR + w]       = bfpair(x0 - bfhi(x0), x1 - bfhi(x1));
        pl[APL + (r + 8) * ASTR + w] = bfpair(x2 - bfhi(x2), x3 - bfhi(x3));
    }
}

// V-GEMM D tile (+bias) -> V^T bf16 hi/lo planes directly (token-pair via shfl)
__device__ __forceinline__ void store_vt(u32* __restrict__ vtpl,
                                         const float* __restrict__ biasg,
                                         int mt, int ng, int lane, float acc[4][4]) {
    const int g = lane >> 2, t = lane & 3;
    const int a = g >> 1;
    const bool even = (g & 1) == 0;
    const int w0 = mt * 8 + a;          // tokens (16mt+2a, +1)
    const int w1 = mt * 8 + 4 + a;      // tokens (16mt+8+2a, +1)
#pragma unroll
    for (int j = 0; j < 4; ++j) {
        const int c = ng * 32 + j * 8 + t * 2;
        float2 bv = *reinterpret_cast<const float2*>(biasg + c);
        float v00 = acc[j][0] + bv.x, v01 = acc[j][1] + bv.y;   // token 16mt+g, cols c, c+1
        float v10 = acc[j][2] + bv.x, v11 = acc[j][3] + bv.y;   // token 16mt+8+g
        float w00 = __shfl_xor_sync(0xffffffffu, v00, 4);
        float w01 = __shfl_xor_sync(0xffffffffu, v01, 4);
        float w10 = __shfl_xor_sync(0xffffffffu, v10, 4);
        float w11 = __shfl_xor_sync(0xffffffffu, v11, 4);
        if (even) {
            vtpl[c * PSTR + w0]             = bfpair(v00, w00);
            vtpl[PPL + c * PSTR + w0]       = bfpair(v00 - bfhi(v00), w00 - bfhi(w00));
            vtpl[(c + 1) * PSTR + w0]       = bfpair(v01, w01);
            vtpl[PPL + (c + 1) * PSTR + w0] = bfpair(v01 - bfhi(v01), w01 - bfhi(w01));
            vtpl[c * PSTR + w1]             = bfpair(v10, w10);
            vtpl[PPL + c * PSTR + w1]       = bfpair(v10 - bfhi(v10), w10 - bfhi(w10));
            vtpl[(c + 1) * PSTR + w1]       = bfpair(v11, w11);
            vtpl[PPL + (c + 1) * PSTR + w1] = bfpair(v11 - bfhi(v11), w11 - bfhi(w11));
        }
    }
}

// scores + in-register softmax -> P planes (no S buffer)
__device__ __forceinline__ void attn_scores_softmax(const u32* __restrict__ qpl,
                                                    const u32* __restrict__ kpl,
                                                    u32* __restrict__ ppl,
                                                    const float* __restrict__ sval,
                                                    float* __restrict__ pmax,
                                                    float* __restrict__ psum,
                                                    int wid, int lane) {
    const int head = wid >> 3, mt = (wid >> 1) & 3, nh = wid & 1;
    const int g = lane >> 2, t = lane & 3;
    float acc[4][4] = {};
    const int rb = (mt * 16 + g) * ASTR + head * 32;
#pragma unroll
    for (int kt = 0; kt < 4; ++kt) {
        const int ca = rb + kt * 8 + t;
        u32 ah0 = qpl[ca],           ah1 = qpl[8 * ASTR + ca];
        u32 ah2 = qpl[ca + 4],       ah3 = qpl[8 * ASTR + ca + 4];
        u32 al0 = qpl[APL + ca],     al1 = qpl[APL + 8 * ASTR + ca];
        u32 al2 = qpl[APL + ca + 4], al3 = qpl[APL + 8 * ASTR + ca + 4];
#pragma unroll
        for (int j = 0; j < 4; ++j) {
            const int kw = (nh * 32 + j * 8 + g) * ASTR + head * 32 + kt * 8 + t;
            u32 bh0 = kpl[kw],       bh1 = kpl[kw + 4];
            u32 bl0 = kpl[APL + kw], bl1 = kpl[APL + kw + 4];
            HMMA(acc[j], ah0, ah1, ah2, ah3, bh0, bh1);
            HMMA(acc[j], al0, al1, al2, al3, bh0, bh1);
            HMMA(acc[j], ah0, ah1, ah2, ah3, bl0, bl1);
        }
    }
    // softmax: rows r0 = head*64 + 16mt + g, r1 = r0 + 8
    const int q0 = mt * 16 + g;
    const int r0 = head * 64 + q0, r1 = r0 + 8;
    const float vq0 = sval[q0], vq1 = sval[q0 + 8];
    float m0 = -3.4e38f, m1 = -3.4e38f;
#pragma unroll
    for (int j = 0; j < 4; ++j) {
        const int c = nh * 32 + j * 8 + 2 * t;
        float2 vk = *reinterpret_cast<const float2*>(sval + c);
        acc[j][0] = acc[j][0] * 0.125f + (1.f - vq0 * vk.x) * -10000.f;
        acc[j][1] = acc[j][1] * 0.125f + (1.f - vq0 * vk.y) * -10000.f;
        acc[j][2] = acc[j][2] * 0.125f + (1.f - vq1 * vk.x) * -10000.f;
        acc[j][3] = acc[j][3] * 0.125f + (1.f - vq1 * vk.y) * -10000.f;
        m0 = fmaxf(m0, fmaxf(acc[j][0], acc[j][1]));
        m1 = fmaxf(m1, fmaxf(acc[j][2], acc[j][3]));
    }
    m0 = fmaxf(m0, __shfl_xor_sync(0xffffffffu, m0, 1));
    m0 = fmaxf(m0, __shfl_xor_sync(0xffffffffu, m0, 2));
    m1 = fmaxf(m1, __shfl_xor_sync(0xffffffffu, m1, 1));
    m1 = fmaxf(m1, __shfl_xor_sync(0xffffffffu, m1, 2));
    if (t == 0) { pmax[nh * 128 + r0] = m0; pmax[nh * 128 + r1] = m1; }
    __syncthreads();
    float gm0 = fmaxf(pmax[r0], pmax[128 + r0]);
    float gm1 = fmaxf(pmax[r1], pmax[128 + r1]);
    float s0 = 0.f, s1 = 0.f;
#pragma unroll
    for (int j = 0; j < 4; ++j) {
        acc[j][0] = __expf(acc[j][0] - gm0); s0 += acc[j][0];
        acc[j][1] = __expf(acc[j][1] - gm0); s0 += acc[j][1];
        acc[j][2] = __expf(acc[j][2] - gm1); s1 += acc[j][2];
        acc[j][3] = __expf(acc[j][3] - gm1); s1 += acc[j][3];
    }
    s0 += __shfl_xor_sync(0xffffffffu, s0, 1);
    s0 += __shfl_xor_sync(0xffffffffu, s0, 2);
    s1 += __shfl_xor_sync(0xffffffffu, s1, 1);
    s1 += __shfl_xor_sync(0xffffffffu, s1, 2);
    if (t == 0) { psum[nh * 128 + r0] = s0; psum[nh * 128 + r1] = s1; }
    __syncthreads();
    const float inv0 = 1.f / (psum[r0] + psum[128 + r0]);
    const float inv1 = 1.f / (psum[r1] + psum[128 + r1]);
#pragma unroll
    for (int j = 0; j < 4; ++j) {
        const int w = nh * 16 + 4 * j + t;
        float p00 = acc[j][0] * inv0, p01 = acc[j][1] * inv0;
        float p10 = acc[j][2] * inv1, p11 = acc[j][3] * inv1;
        ppl[r0 * PSTR + w]       = bfpair(p00, p01);
        ppl[PPL + r0 * PSTR + w] = bfpair(p00 - bfhi(p00), p01 - bfhi(p01));
        ppl[r1 * PSTR + w]       = bfpair(p10, p11);
        ppl[PPL + r1 * PSTR + w] = bfpair(p10 - bfhi(p10), p11 - bfhi(p11));
    }
}

// ctx = P @ V -> fp32 scratch (pitch 132) (proven)
__device__ __forceinline__ void attn_ctx(const u32* __restrict__ ppl,
                                         const u32* __restrict__ vtpl,
                                         float* __restrict__ ctx,
                                         int wid, int lane) {
    const int mt = wid & 3, ng = wid >> 2;
    const int head = ng >> 1;
    const int g = lane >> 2, t = lane & 3;
    float acc[4][4] = {};
    const int rb = (head * 64 + mt * 16 + g) * PSTR;
#pragma unroll
    for (int kt = 0; kt < 4; ++kt) {
        const int ca = rb + kt * 8 + t;
        u32 ah0 = ppl[ca],           ah1 = ppl[8 * PSTR + ca];
        u32 ah2 = ppl[ca + 4],       ah3 = ppl[8 * PSTR + ca + 4];
        u32 al0 = ppl[PPL + ca],     al1 = ppl[PPL + 8 * PSTR + ca];
        u32 al2 = ppl[PPL + ca + 4], al3 = ppl[PPL + 8 * PSTR + ca + 4];
#pragma unroll
        for (int j = 0; j < 4; ++j) {
            const int vw = (ng * 32 + j * 8 + g) * PSTR + kt * 8 + t;
            u32 bh0 = vtpl[vw],       bh1 = vtpl[vw + 4];
            u32 bl0 = vtpl[PPL + vw], bl1 = vtpl[PPL + vw + 4];
            HMMA(acc[j], ah0, ah1, ah2, ah3, bh0, bh1);
            HMMA(acc[j], al0, al1, al2, al3, bh0, bh1);
            HMMA(acc[j], ah0, ah1, ah2, ah3, bl0, bl1);
        }
    }
    const int r = mt * 16 + g;
#pragma unroll
    for (int j = 0; j < 4; ++j) {
        const int c = ng * 32 + j * 8 + 2 * t;
        *reinterpret_cast<float2*>(ctx + r * 132 + c)       = make_float2(acc[j][0], acc[j][1]);
        *reinterpret_cast<float2*>(ctx + (r + 8) * 132 + c) = make_float2(acc[j][2], acc[j][3]);
    }
}

// K=16 emb gemm, 4 tokens, x from global (proven)
__device__ __forceinline__ void gemm16(const float4* __restrict__ wp4,
                                       const float4* __restrict__ xg4,
                                       int t0, int l, float4 bias, float4 res[4]) {
    u64 acc[4][4] = {};
#pragma unroll
    for (int kb = 0; kb < 4; ++kb) {
        const float4* w0 = wp4 + (2 * kb) * 64 + 2 * l;
        const float4* w1 = wp4 + (2 * kb + 1) * 64 + 2 * l;
        F4 A0, A1, B0, B1;
        A0.v = w0[0]; A1.v = w0[1]; B0.v = w1[0]; B1.v = w1[1];
#pragma unroll
        for (int t = 0; t < 4; ++t) {
            F4 x; x.v = xg4[(t0 + t) * 4 + kb];
            ffma2(acc[t][0], x.u[0], A0.u[0]); ffma2(acc[t][0], x.u[1], B0.u[0]);
            ffma2(acc[t][1], x.u[0], A0.u[1]); ffma2(acc[t][1], x.u[1], B0.u[1]);
            ffma2(acc[t][2], x.u[0], A1.u[0]); ffma2(acc[t][2], x.u[1], B1.u[0]);
            ffma2(acc[t][3], x.u[0], A1.u[1]); ffma2(acc[t][3], x.u[1], B1.u[1]);
        }
    }
#pragma unroll
    for (int t = 0; t < 4; ++t)
        res[t] = make_float4(hsum2(acc[t][0]) + bias.x, hsum2(acc[t][1]) + bias.y,
                             hsum2(acc[t][2]) + bias.z, hsum2(acc[t][3]) + bias.w);
}

// ================= main fused kernel: 1 sequence per CTA =================
__global__ void __launch_bounds__(NT, 1) fused_lane_encoder(
    const float* __restrict__ feat, const float* __restrict__ masks,
    const float* __restrict__ b_emb, const float* __restrict__ g_emb,
    const float* __restrict__ beta_emb,
    const float* __restrict__ b_enc, const float* __restrict__ g_enc,
    const float* __restrict__ beta_enc,
    const float* __restrict__ bq, const float* __restrict__ bk,
    const float* __restrict__ bv,
    const float* __restrict__ ln_g, const float* __restrict__ ln_b,
    float* __restrict__ out)
{
    extern __shared__ float smem[];
    float* const hs   = smem + OFF_HS;
    u32*   const ahl  = reinterpret_cast<u32*>(smem + OFF_AHL);
    u32*   const VT   = reinterpret_cast<u32*>(smem + OFF_VT);
    u32*   const QP   = reinterpret_cast<u32*>(smem + OFF_QP);
    u32*   const KP   = reinterpret_cast<u32*>(smem + OFF_KP);   // K planes, then P planes
    float* const RC   = smem + OFF_RC;
    float* const sval = smem + OFF_SVAL;
    float* const pmax = smem + OFF_PMX;
    float* const psum = smem + OFF_PSM;

    float4* const hs4 = reinterpret_cast<float4*>(hs);

    const int tid  = threadIdx.x;
    const int lane = tid & 31;
    const int wid  = tid >> 5;       // 0..15
    const int mt   = wid & 3;
    const int ng   = wid >> 2;
    const int blk  = blockIdx.x;

    if (tid < 64) sval[tid] = 1.0f - masks[(size_t)blk * 64 + tid];

    // ---- Phase 1: emb = relu(LN(feat @ W_emb + b)); warp owns 4 tokens ----
    {
        const float4* fg4 = reinterpret_cast<const float4*>(feat + (size_t)blk * 64 * IN_);
        const float4* we4 = reinterpret_cast<const float4*>(g_wemb);
        float4 bias = *reinterpret_cast<const float4*>(b_emb + 4 * lane);
        float4 gm   = *reinterpret_cast<const float4*>(g_emb + 4 * lane);
        float4 bt   = *reinterpret_cast<const float4*>(beta_emb + 4 * lane);
        int t0 = wid * 4;
        float4 r[4];
        gemm16(we4, fg4, t0, lane, bias, r);
#pragma unroll
        for (int t = 0; t < 4; ++t) {
            float4 y = ln_warp(r[t], gm, bt);
            y = make_float4(fmaxf(y.x, 0.f), fmaxf(y.y, 0.f), fmaxf(y.z, 0.f), fmaxf(y.w, 0.f));
            hs4[(t0 + t) * 32 + lane] = y;
            store_ahl(ahl, t0 + t, lane, y);
        }
    }
    __syncthreads();

    // ---- Phase 2: enc GEMM -> RC, then LN/relu -> hs + ahl ----
    {
        float acc[4][4];
        gemm_mma(ahl, reinterpret_cast<const u64*>(g_bw), mt, ng, lane, acc);
        store_tile(RC, b_enc, mt, ng, lane, acc);
    }
    __syncthreads();
    {
        const float4* rc4 = reinterpret_cast<const float4*>(RC);
        float4 gm = *reinterpret_cast<const float4*>(g_enc + 4 * lane);
        float4 bt = *reinterpret_cast<const float4*>(beta_enc + 4 * lane);
        int t0 = wid * 4;
#pragma unroll
        for (int t = 0; t < 4; ++t) {
            float4 x = rc4[(t0 + t) * 33 + lane];
            float4 y = ln_warp(x, gm, bt);
            y = make_float4(fmaxf(y.x, 0.f), fmaxf(y.y, 0.f), fmaxf(y.z, 0.f), fmaxf(y.w, 0.f));
            hs4[(t0 + t) * 32 + lane] = y;
            store_ahl(ahl, t0 + t, lane, y);
        }
    }
    __syncthreads();

    // ---- Phase 3: transformer layers (fully HMMA) ----
    for (int d = 0; d < 3; ++d) {
        {
            const u64* base = reinterpret_cast<const u64*>(g_bw);
            float acc[4][4];
            gemm_mma(ahl, base + (size_t)(3 + 3 * d) * 8192, mt, ng, lane, acc);
            store_vt(VT, bv + d * H_, mt, ng, lane, acc);           // V^T planes (direct)
            gemm_mma(ahl, base + (size_t)(1 + 3 * d) * 8192, mt, ng, lane, acc);
            store_planes(QP, bq + d * H_, mt, ng, lane, acc);       // Q planes
            gemm_mma(ahl, base + (size_t)(2 + 3 * d) * 8192, mt, ng, lane, acc);
            store_planes(KP, bk + d * H_, mt, ng, lane, acc);       // K planes
        }
        __syncthreads();

        attn_scores_softmax(QP, KP, KP, sval, pmax, psum, wid, lane);  // P overlays K planes
        __syncthreads();

        attn_ctx(KP, VT, RC, wid, lane);
        __syncthreads();

        {   // residual + LN epilogue (warp-local)
            const float4* rc4 = reinterpret_cast<const float4*>(RC);
            float4 gm = *reinterpret_cast<const float4*>(ln_g + d * H_ + 4 * lane);
            float4 bt = *reinterpret_cast<const float4*>(ln_b + d * H_ + 4 * lane);
            int t0 = wid * 4;
#pragma unroll
            for (int t = 0; t < 4; ++t) {
                int row = t0 + t;
                float4 cv = rc4[row * 33 + lane];
                float4 hv = hs4[row * 32 + lane];
                float4 x = make_float4(fmaxf(cv.x, 0.f) + hv.x, fmaxf(cv.y, 0.f) + hv.y,
                                       fmaxf(cv.z, 0.f) + hv.z, fmaxf(cv.w, 0.f) + hv.w);
                float4 y = ln_warp(x, gm, bt);
                hs4[row * 32 + lane] = y;
                if (d < 2) store_ahl(ahl, row, lane, y);
            }
        }
        __syncthreads();
    }

    // ---- Phase 4: max over T (scratch = RC) ----
    {
        const int part = tid >> 7;
        const int hh   = tid & 127;
        float m = -3.4e38f;
#pragma unroll
        for (int t = 0; t < 16; ++t)
            m = fmaxf(m, hs[(part * 16 + t) * H_ + hh]);
        RC[part * H_ + hh] = m;
    }
    __syncthreads();
    if (tid < H_)
        out[(size_t)blk * H_ + tid] = fmaxf(fmaxf(RC[tid], RC[H_ + tid]),
                                            fmaxf(RC[2 * H_ + tid], RC[3 * H_ + tid]));
}

} // namespace

extern "C" void kernel_launch(void* const* d_in, const int* in_sizes, int n_in,
                              void* d_out, int out_size) {
    const float* feat     = (const float*)d_in[0];
    const float* masks    = (const float*)d_in[1];
    const float* W_emb    = (const float*)d_in[2];
    const float* b_emb    = (const float*)d_in[3];
    const float* g_emb    = (const float*)d_in[4];
    const float* beta_emb = (const float*)d_in[5];
    const float* W_enc    = (const float*)d_in[6];
    const float* b_enc    = (const float*)d_in[7];
    const float* g_enc    = (const float*)d_in[8];
    const float* beta_enc = (const float*)d_in[9];
    const float* Wq       = (const float*)d_in[10];
    const float* bq       = (const float*)d_in[11];
    const float* Wk       = (const float*)d_in[12];
    const float* bk       = (const float*)d_in[13];
    const float* Wv       = (const float*)d_in[14];
    const float* bv       = (const float*)d_in[15];
    const float* ln_g     = (const float*)d_in[16];
    const float* ln_b     = (const float*)d_in[17];
    float* out = (float*)d_out;

    int nseq = in_sizes[0] / (64 * IN_);   // 4096
    pack_all<<<(1024 + BW_U32 + 255) / 256, 256>>>(W_emb, W_enc, Wq, Wk, Wv);

    size_t smem = (size_t)SM_FLOATS * 4;   // ~212KB
    cudaFuncSetAttribute(fused_lane_encoder,
                         cudaFuncAttributeMaxDynamicSharedMemorySize, (int)smem);
    fused_lane_encoder<<<nseq, NT, smem>>>(
        feat, masks, b_emb, g_emb, beta_emb, b_enc, g_enc, beta_enc,
        bq, bk, bv, ln_g, ln_b, out);
}

// round 17
// speedup vs baseline: 1.2778x; 1.0501x over previous
#include <cuda_runtime.h>
#include <cuda_bf16.h>

namespace {

typedef unsigned long long u64;
typedef unsigned int u32;

constexpr int IN_ = 16;
constexpr int H_ = 128;
constexpr int NT = 512;
constexpr float EPS = 1e-5f;
constexpr int ASTR = 68;          // bf16-plane row stride in u32 words (64 data + 4 pad; %32==4 -> conflict-free)
constexpr int APL = 64 * ASTR;    // hi->lo plane offset for 64-row planes (u32 words)
constexpr int APL4 = APL * 4;     // same, bytes
constexpr int PSTR = 36;          // P / V^T plane row stride in u32 words (32 data + 4 pad)
constexpr int PPL = 128 * PSTR;   // hi->lo plane offset for 128-row planes
constexpr int PPL4 = PPL * 4;

// smem float offsets
constexpr int OFF_HS   = 0;        // 64x128 fp32 residual
constexpr int OFF_AHL  = 8192;     // activation bf16 hi/lo planes (2*APL u32 = 8704)
constexpr int OFF_VT   = 16896;    // V^T planes (2*PPL = 9216)
constexpr int OFF_QP   = 26112;    // Q planes (2*APL = 8704)
constexpr int OFF_KP   = 34816;    // K planes -> P planes (max(2*APL, 2*PPL) = 9216)
constexpr int OFF_RC   = 44032;    // enc scratch / ctx scratch (64x132 = 8448)
constexpr int OFF_SVAL = 52480;    // 64
constexpr int OFF_PMX  = 52544;    // 2 x 128 row-max exchange
constexpr int OFF_PSM  = 52800;    // 2 x 128 row-sum exchange
constexpr int SM_FLOATS = 53056;   // ~212KB

// B fragments packed for mma.m16n8k16 as 16B chunks:
// u32 index = (((m*8 + kt)*16 + nt)*32 + lane)*4 + w,  w: 0,1 = bh0,bh1  2,3 = bl0,bl1
constexpr int BW_U32 = 10 * 8 * 16 * 32 * 4;
__device__ __align__(16) u32 g_bw[BW_U32];
__device__ __align__(16) float2 g_wemb[8 * 128];

__device__ __forceinline__ u32 bfpair(float lo, float hi) {
    u32 r; asm("cvt.rn.bf16x2.f32 %0, %1, %2;" : "=r"(r) : "f"(hi), "f"(lo)); return r;
}
__device__ __forceinline__ float bfhi(float x) {
    return __bfloat162float(__float2bfloat16(x));
}

__global__ void pack_all(const float* __restrict__ Wemb, const float* __restrict__ We,
                         const float* __restrict__ Wq, const float* __restrict__ Wk,
                         const float* __restrict__ Wv) {
    int i = blockIdx.x * 256 + threadIdx.x;
    if (i < 1024) {
        int h = i & 127, m = i >> 7;
        g_wemb[i] = make_float2(Wemb[(2 * m) * H_ + h], Wemb[(2 * m + 1) * H_ + h]);
        return;
    }
    int j = i - 1024;
    if (j >= BW_U32) return;
    int w    = j & 3;
    int lane = (j >> 2) & 31;
    int nt   = (j >> 7) & 15;
    int kt   = (j >> 11) & 7;
    int m    = j >> 14;
    const float* src;
    if (m == 0) src = We;
    else { int r = m - 1, d = r / 3, ww = r % 3;
           src = (ww == 0 ? Wq : (ww == 1 ? Wk : Wv)) + d * H_ * H_; }
    int s = w >> 1, reg = w & 1;
    int k0 = kt * 16 + (lane & 3) * 2 + reg * 8;
    int n  = nt * 8 + (lane >> 2);
    float x0 = src[k0 * H_ + n], x1 = src[(k0 + 1) * H_ + n];
    if (s) { x0 -= bfhi(x0); x1 -= bfhi(x1); }
    g_bw[j] = bfpair(x0, x1);
}

// ---------------- scalar helpers (proven) ----------------
union F4 { float4 v; u64 u[2]; };
__device__ __forceinline__ void ffma2(u64& d, u64 a, u64 b) {
    asm("fma.rn.f32x2 %0, %1, %2, %0;" : "+l"(d) : "l"(a), "l"(b));
}
__device__ __forceinline__ float hsum2(u64 v) {
    float lo, hi; asm("mov.b64 {%0, %1}, %2;" : "=f"(lo), "=f"(hi) : "l"(v));
    return lo + hi;
}
__device__ __forceinline__ float warp_sum(float v) {
#pragma unroll
    for (int o = 16; o > 0; o >>= 1) v += __shfl_xor_sync(0xffffffffu, v, o);
    return v;
}
__device__ __forceinline__ float4 ln_warp(float4 x, float4 gm, float4 bt) {
    float s  = warp_sum(x.x + x.y + x.z + x.w);
    float ss = warp_sum(x.x * x.x + x.y * x.y + x.z * x.z + x.w * x.w);
    float mean = s * (1.f / H_);
    float inv  = rsqrtf(ss * (1.f / H_) - mean * mean + EPS);
    return make_float4(gm.x * (x.x - mean) * inv + bt.x, gm.y * (x.y - mean) * inv + bt.y,
                       gm.z * (x.z - mean) * inv + bt.z, gm.w * (x.w - mean) * inv + bt.w);
}
__device__ __forceinline__ u32 smem_u32(const void* p) {
    u32 a;
    asm("{ .reg .u64 t; cvta.to.shared.u64 t, %1; cvt.u32.u64 %0, t; }" : "=r"(a) : "l"(p));
    return a;
}

// write bf16 hi/lo planes of one row-slice (cols 4l..4l+3)
__device__ __forceinline__ void store_ahl(u32* __restrict__ ahl, int row, int l, float4 y) {
    u32 h0 = bfpair(y.x, y.y), h1 = bfpair(y.z, y.w);
    u32 l0 = bfpair(y.x - bfhi(y.x), y.y - bfhi(y.y));
    u32 l1 = bfpair(y.z - bfhi(y.z), y.w - bfhi(y.w));
    *reinterpret_cast<u64*>(ahl + row * ASTR + 2 * l)       = (u64)h0 | ((u64)h1 << 32);
    *reinterpret_cast<u64*>(ahl + APL + row * ASTR + 2 * l) = (u64)l0 | ((u64)l1 << 32);
}

#define HMMA(d, a0, a1, a2, a3, b0, b1) \
    asm volatile("mma.sync.aligned.m16n8k16.row.col.f32.bf16.bf16.f32 " \
        "{%0,%1,%2,%3},{%4,%5,%6,%7},{%8,%9},{%0,%1,%2,%3};" \
        : "+f"((d)[0]), "+f"((d)[1]), "+f"((d)[2]), "+f"((d)[3]) \
        : "r"(a0), "r"(a1), "r"(a2), "r"(a3), "r"(b0), "r"(b1))

#define LDSM4(r0, r1, r2, r3, ad) \
    asm volatile("ldmatrix.sync.aligned.m8n8.x4.shared.b16 {%0,%1,%2,%3}, [%4];" \
        : "=r"(r0), "=r"(r1), "=r"(r2), "=r"(r3) : "r"(ad))

// one 64x128x128 GEMM tile-slice; A via ldmatrix, B via LDG.128
__device__ __forceinline__ void gemm_mma(u32 ahl_ad, const uint4* __restrict__ bw4,
                                         int mt, int ng, int lane, float acc[4][4]) {
#pragma unroll
    for (int j = 0; j < 4; ++j)
#pragma unroll
        for (int r = 0; r < 4; ++r) acc[j][r] = 0.f;
    const int r8 = lane & 7, m8 = lane >> 3;
    // A frag addr: mat0 rows g / k-left, mat1 rows g+8, mat2 k-right, mat3 both
    const u32 a_hi = ahl_ad + (u32)(((mt * 16 + r8 + (m8 & 1) * 8) * ASTR + (m8 >> 1) * 4) * 4);
#pragma unroll
    for (int kt = 0; kt < 8; ++kt) {
        u32 ah0, ah1, ah2, ah3, al0, al1, al2, al3;
        LDSM4(ah0, ah1, ah2, ah3, a_hi + kt * 32);
        LDSM4(al0, al1, al2, al3, a_hi + APL4 + kt * 32);
#pragma unroll
        for (int j = 0; j < 4; ++j) {
            const int nt = ng * 4 + j;
            uint4 b = bw4[(kt * 16 + nt) * 32 + lane];
            HMMA(acc[j], ah0, ah1, ah2, ah3, b.x, b.y);
            HMMA(acc[j], al0, al1, al2, al3, b.x, b.y);
            HMMA(acc[j], ah0, ah1, ah2, ah3, b.z, b.w);
        }
    }
}

// D tile (+bias) -> pitched fp32 buffer (132-float rows) (proven)
__device__ __forceinline__ void store_tile(float* __restrict__ buf,
                                           const float* __restrict__ biasg,
                                           int mt, int ng, int lane, float acc[4][4]) {
    const int g = lane >> 2, q = lane & 3;
#pragma unroll
    for (int j = 0; j < 4; ++j) {
        const int c = ng * 32 + j * 8 + q * 2;
        float2 bv = *reinterpret_cast<const float2*>(biasg + c);
        const int r = mt * 16 + g;
        *reinterpret_cast<float2*>(buf + r * 132 + c) =
            make_float2(acc[j][0] + bv.x, acc[j][1] + bv.y);
        *reinterpret_cast<float2*>(buf + (r + 8) * 132 + c) =
            make_float2(acc[j][2] + bv.x, acc[j][3] + bv.y);
    }
}

// D tile (+bias) -> bf16 hi/lo planes for Q/K (proven)
__device__ __forceinline__ void store_planes(u32* __restrict__ pl,
                                             const float* __restrict__ biasg,
                                             int mt, int ng, int lane, float acc[4][4]) {
    const int g = lane >> 2, t = lane & 3;
    const int r = mt * 16 + g;
#pragma unroll
    for (int j = 0; j < 4; ++j) {
        const int c = ng * 32 + j * 8 + t * 2;
        float2 bv = *reinterpret_cast<const float2*>(biasg + c);
        const int w = ng * 16 + j * 4 + t;
        float x0 = acc[j][0] + bv.x, x1 = acc[j][1] + bv.y;
        float x2 = acc[j][2] + bv.x, x3 = acc[j][3] + bv.y;
        pl[r * ASTR + w]             = bfpair(x0, x1);
        pl[(r + 8) * ASTR + w]       = bfpair(x2, x3);
        pl[APL + r * ASTR + w]       = bfpair(x0 - bfhi(x0), x1 - bfhi(x1));
        pl[APL + (r + 8) * ASTR + w] = bfpair(x2 - bfhi(x2), x3 - bfhi(x3));
    }
}

// V-GEMM D tile (+bias) -> V^T bf16 hi/lo planes directly (proven)
__device__ __forceinline__ void store_vt(u32* __restrict__ vtpl,
                                         const float* __restrict__ biasg,
                                         int mt, int ng, int lane, float acc[4][4]) {
    const int g = lane >> 2, t = lane & 3;
    const int a = g >> 1;
    const bool even = (g & 1) == 0;
    const int w0 = mt * 8 + a;
    const int w1 = mt * 8 + 4 + a;
#pragma unroll
    for (int j = 0; j < 4; ++j) {
        const int c = ng * 32 + j * 8 + t * 2;
        float2 bv = *reinterpret_cast<const float2*>(biasg + c);
        float v00 = acc[j][0] + bv.x, v01 = acc[j][1] + bv.y;
        float v10 = acc[j][2] + bv.x, v11 = acc[j][3] + bv.y;
        float w00 = __shfl_xor_sync(0xffffffffu, v00, 4);
        float w01 = __shfl_xor_sync(0xffffffffu, v01, 4);
        float w10 = __shfl_xor_sync(0xffffffffu, v10, 4);
        float w11 = __shfl_xor_sync(0xffffffffu, v11, 4);
        if (even) {
            vtpl[c * PSTR + w0]             = bfpair(v00, w00);
            vtpl[PPL + c * PSTR + w0]       = bfpair(v00 - bfhi(v00), w00 - bfhi(w00));
            vtpl[(c + 1) * PSTR + w0]       = bfpair(v01, w01);
            vtpl[PPL + (c + 1) * PSTR + w0] = bfpair(v01 - bfhi(v01), w01 - bfhi(w01));
            vtpl[c * PSTR + w1]             = bfpair(v10, w10);
            vtpl[PPL + c * PSTR + w1]       = bfpair(v10 - bfhi(v10), w10 - bfhi(w10));
            vtpl[(c + 1) * PSTR + w1]       = bfpair(v11, w11);
            vtpl[PPL + (c + 1) * PSTR + w1] = bfpair(v11 - bfhi(v11), w11 - bfhi(w11));
        }
    }
}

// scores + in-register softmax -> P planes; all frag loads via ldmatrix
__device__ __forceinline__ void attn_scores_softmax(u32 qp_ad, u32 kp_ad,
                                                    u32* __restrict__ ppl,
                                                    const float* __restrict__ sval,
                                                    float* __restrict__ pmax,
                                                    float* __restrict__ psum,
                                                    int wid, int lane) {
    const int head = wid >> 3, mt = (wid >> 1) & 3, nh = wid & 1;
    const int g = lane >> 2, t = lane & 3;
    const int r8 = lane & 7, m8 = lane >> 3;
    float acc[4][4] = {};
    // Q (A-frag): rows mt*16.., word base head*32
    const u32 qa = qp_ad + (u32)(((mt * 16 + r8 + (m8 & 1) * 8) * ASTR + head * 32 + (m8 >> 1) * 4) * 4);
    // K (B-frag x4 = j-pair): mat m: rows nh*32 + (m>>1)*8 + r8, word head*32 + (m&1)*4
    const u32 ka = kp_ad + (u32)(((nh * 32 + (m8 >> 1) * 8 + r8) * ASTR + head * 32 + (m8 & 1) * 4) * 4);
    const u32 j2o = 16 * ASTR * 4;
#pragma unroll
    for (int kt = 0; kt < 4; ++kt) {
        u32 qh0, qh1, qh2, qh3, ql0, ql1, ql2, ql3;
        LDSM4(qh0, qh1, qh2, qh3, qa + kt * 32);
        LDSM4(ql0, ql1, ql2, ql3, qa + APL4 + kt * 32);
        u32 kh[8], kl[8];
        LDSM4(kh[0], kh[1], kh[2], kh[3], ka + kt * 32);
        LDSM4(kh[4], kh[5], kh[6], kh[7], ka + j2o + kt * 32);
        LDSM4(kl[0], kl[1], kl[2], kl[3], ka + APL4 + kt * 32);
        LDSM4(kl[4], kl[5], kl[6], kl[7], ka + APL4 + j2o + kt * 32);
#pragma unroll
        for (int j = 0; j < 4; ++j) {
            HMMA(acc[j], qh0, qh1, qh2, qh3, kh[2 * j], kh[2 * j + 1]);
            HMMA(acc[j], ql0, ql1, ql2, ql3, kh[2 * j], kh[2 * j + 1]);
            HMMA(acc[j], qh0, qh1, qh2, qh3, kl[2 * j], kl[2 * j + 1]);
        }
    }
    // softmax: rows r0 = head*64 + 16mt + g, r1 = r0 + 8
    const int q0 = mt * 16 + g;
    const int r0 = head * 64 + q0, r1 = r0 + 8;
    const float vq0 = sval[q0], vq1 = sval[q0 + 8];
    float m0 = -3.4e38f, m1 = -3.4e38f;
#pragma unroll
    for (int j = 0; j < 4; ++j) {
        const int c = nh * 32 + j * 8 + 2 * t;
        float2 vk = *reinterpret_cast<const float2*>(sval + c);
        acc[j][0] = acc[j][0] * 0.125f + (1.f - vq0 * vk.x) * -10000.f;
        acc[j][1] = acc[j][1] * 0.125f + (1.f - vq0 * vk.y) * -10000.f;
        acc[j][2] = acc[j][2] * 0.125f + (1.f - vq1 * vk.x) * -10000.f;
        acc[j][3] = acc[j][3] * 0.125f + (1.f - vq1 * vk.y) * -10000.f;
        m0 = fmaxf(m0, fmaxf(acc[j][0], acc[j][1]));
        m1 = fmaxf(m1, fmaxf(acc[j][2], acc[j][3]));
    }
    m0 = fmaxf(m0, __shfl_xor_sync(0xffffffffu, m0, 1));
    m0 = fmaxf(m0, __shfl_xor_sync(0xffffffffu, m0, 2));
    m1 = fmaxf(m1, __shfl_xor_sync(0xffffffffu, m1, 1));
    m1 = fmaxf(m1, __shfl_xor_sync(0xffffffffu, m1, 2));
    if (t == 0) { pmax[nh * 128 + r0] = m0; pmax[nh * 128 + r1] = m1; }
    __syncthreads();
    float gm0 = fmaxf(pmax[r0], pmax[128 + r0]);
    float gm1 = fmaxf(pmax[r1], pmax[128 + r1]);
    float s0 = 0.f, s1 = 0.f;
#pragma unroll
    for (int j = 0; j < 4; ++j) {
        acc[j][0] = __expf(acc[j][0] - gm0); s0 += acc[j][0];
        acc[j][1] = __expf(acc[j][1] - gm0); s0 += acc[j][1];
        acc[j][2] = __expf(acc[j][2] - gm1); s1 += acc[j][2];
        acc[j][3] = __expf(acc[j][3] - gm1); s1 += acc[j][3];
    }
    s0 += __shfl_xor_sync(0xffffffffu, s0, 1);
    s0 += __shfl_xor_sync(0xffffffffu, s0, 2);
    s1 += __shfl_xor_sync(0xffffffffu, s1, 1);
    s1 += __shfl_xor_sync(0xffffffffu, s1, 2);
    if (t == 0) { psum[nh * 128 + r0] = s0; psum[nh * 128 + r1] = s1; }
    __syncthreads();
    const float inv0 = 1.f / (psum[r0] + psum[128 + r0]);
    const float inv1 = 1.f / (psum[r1] + psum[128 + r1]);
#pragma unroll
    for (int j = 0; j < 4; ++j) {
        const int w = nh * 16 + 4 * j + t;
        float p00 = acc[j][0] * inv0, p01 = acc[j][1] * inv0;
        float p10 = acc[j][2] * inv1, p11 = acc[j][3] * inv1;
        ppl[r0 * PSTR + w]       = bfpair(p00, p01);
        ppl[PPL + r0 * PSTR + w] = bfpair(p00 - bfhi(p00), p01 - bfhi(p01));
        ppl[r1 * PSTR + w]       = bfpair(p10, p11);
        ppl[PPL + r1 * PSTR + w] = bfpair(p10 - bfhi(p10), p11 - bfhi(p11));
    }
}

// ctx = P @ V -> fp32 scratch; frag loads via ldmatrix
__device__ __forceinline__ void attn_ctx(u32 pp_ad, u32 vt_ad,
                                         float* __restrict__ ctx,
                                         int wid, int lane) {
    const int mt = wid & 3, ng = wid >> 2;
    const int head = ng >> 1;
    const int g = lane >> 2, t = lane & 3;
    const int r8 = lane & 7, m8 = lane >> 3;
    float acc[4][4] = {};
    const u32 pa = pp_ad + (u32)(((head * 64 + mt * 16 + r8 + (m8 & 1) * 8) * PSTR + (m8 >> 1) * 4) * 4);
    const u32 va = vt_ad + (u32)(((ng * 32 + (m8 >> 1) * 8 + r8) * PSTR + (m8 & 1) * 4) * 4);
    const u32 j2o = 16 * PSTR * 4;
#pragma unroll
    for (int kt = 0; kt < 4; ++kt) {
        u32 ph0, ph1, ph2, ph3, pl0, pl1, pl2, pl3;
        LDSM4(ph0, ph1, ph2, ph3, pa + kt * 32);
        LDSM4(pl0, pl1, pl2, pl3, pa + PPL4 + kt * 32);
        u32 vh[8], vl[8];
        LDSM4(vh[0], vh[1], vh[2], vh[3], va + kt * 32);
        LDSM4(vh[4], vh[5], vh[6], vh[7], va + j2o + kt * 32);
        LDSM4(vl[0], vl[1], vl[2], vl[3], va + PPL4 + kt * 32);
        LDSM4(vl[4], vl[5], vl[6], vl[7], va + PPL4 + j2o + kt * 32);
#pragma unroll
        for (int j = 0; j < 4; ++j) {
            HMMA(acc[j], ph0, ph1, ph2, ph3, vh[2 * j], vh[2 * j + 1]);
            HMMA(acc[j], pl0, pl1, pl2, pl3, vh[2 * j], vh[2 * j + 1]);
            HMMA(acc[j], ph0, ph1, ph2, ph3, vl[2 * j], vl[2 * j + 1]);
        }
    }
    const int r = mt * 16 + g;
#pragma unroll
    for (int j = 0; j < 4; ++j) {
        const int c = ng * 32 + j * 8 + 2 * t;
        *reinterpret_cast<float2*>(ctx + r * 132 + c)       = make_float2(acc[j][0], acc[j][1]);
        *reinterpret_cast<float2*>(ctx + (r + 8) * 132 + c) = make_float2(acc[j][2], acc[j][3]);
    }
}

// K=16 emb gemm, 4 tokens, x from global (proven)
__device__ __forceinline__ void gemm16(const float4* __restrict__ wp4,
                                       const float4* __restrict__ xg4,
                                       int t0, int l, float4 bias, float4 res[4]) {
    u64 acc[4][4] = {};
#pragma unroll
    for (int kb = 0; kb < 4; ++kb) {
        const float4* w0 = wp4 + (2 * kb) * 64 + 2 * l;
        const float4* w1 = wp4 + (2 * kb + 1) * 64 + 2 * l;
        F4 A0, A1, B0, B1;
        A0.v = w0[0]; A1.v = w0[1]; B0.v = w1[0]; B1.v = w1[1];
#pragma unroll
        for (int t = 0; t < 4; ++t) {
            F4 x; x.v = xg4[(t0 + t) * 4 + kb];
            ffma2(acc[t][0], x.u[0], A0.u[0]); ffma2(acc[t][0], x.u[1], B0.u[0]);
            ffma2(acc[t][1], x.u[0], A0.u[1]); ffma2(acc[t][1], x.u[1], B0.u[1]);
            ffma2(acc[t][2], x.u[0], A1.u[0]); ffma2(acc[t][2], x.u[1], B1.u[0]);
            ffma2(acc[t][3], x.u[0], A1.u[1]); ffma2(acc[t][3], x.u[1], B1.u[1]);
        }
    }
#pragma unroll
    for (int t = 0; t < 4; ++t)
        res[t] = make_float4(hsum2(acc[t][0]) + bias.x, hsum2(acc[t][1]) + bias.y,
                             hsum2(acc[t][2]) + bias.z, hsum2(acc[t][3]) + bias.w);
}

// ================= main fused kernel: 1 sequence per CTA =================
__global__ void __launch_bounds__(NT, 1) fused_lane_encoder(
    const float* __restrict__ feat, const float* __restrict__ masks,
    const float* __restrict__ b_emb, const float* __restrict__ g_emb,
    const float* __restrict__ beta_emb,
    const float* __restrict__ b_enc, const float* __restrict__ g_enc,
    const float* __restrict__ beta_enc,
    const float* __restrict__ bq, const float* __restrict__ bk,
    const float* __restrict__ bv,
    const float* __restrict__ ln_g, const float* __restrict__ ln_b,
    float* __restrict__ out)
{
    extern __shared__ float smem[];
    float* const hs   = smem + OFF_HS;
    u32*   const ahl  = reinterpret_cast<u32*>(smem + OFF_AHL);
    u32*   const VT   = reinterpret_cast<u32*>(smem + OFF_VT);
    u32*   const QP   = reinterpret_cast<u32*>(smem + OFF_QP);
    u32*   const KP   = reinterpret_cast<u32*>(smem + OFF_KP);   // K planes, then P planes
    float* const RC   = smem + OFF_RC;
    float* const sval = smem + OFF_SVAL;
    float* const pmax = smem + OFF_PMX;
    float* const psum = smem + OFF_PSM;

    float4* const hs4 = reinterpret_cast<float4*>(hs);
    const u32 ahl_ad = smem_u32(ahl);
    const u32 vt_ad  = smem_u32(VT);
    const u32 qp_ad  = smem_u32(QP);
    const u32 kp_ad  = smem_u32(KP);

    const int tid  = threadIdx.x;
    const int lane = tid & 31;
    const int wid  = tid >> 5;       // 0..15
    const int mt   = wid & 3;
    const int ng   = wid >> 2;
    const int blk  = blockIdx.x;

    if (tid < 64) sval[tid] = 1.0f - masks[(size_t)blk * 64 + tid];

    // ---- Phase 1: emb = relu(LN(feat @ W_emb + b)); warp owns 4 tokens ----
    {
        const float4* fg4 = reinterpret_cast<const float4*>(feat + (size_t)blk * 64 * IN_);
        const float4* we4 = reinterpret_cast<const float4*>(g_wemb);
        float4 bias = *reinterpret_cast<const float4*>(b_emb + 4 * lane);
        float4 gm   = *reinterpret_cast<const float4*>(g_emb + 4 * lane);
        float4 bt   = *reinterpret_cast<const float4*>(beta_emb + 4 * lane);
        int t0 = wid * 4;
        float4 r[4];
        gemm16(we4, fg4, t0, lane, bias, r);
#pragma unroll
        for (int t = 0; t < 4; ++t) {
            float4 y = ln_warp(r[t], gm, bt);
            y = make_float4(fmaxf(y.x, 0.f), fmaxf(y.y, 0.f), fmaxf(y.z, 0.f), fmaxf(y.w, 0.f));
            hs4[(t0 + t) * 32 + lane] = y;
            store_ahl(ahl, t0 + t, lane, y);
        }
    }
    __syncthreads();

    // ---- Phase 2: enc GEMM -> RC, then LN/relu -> hs + ahl ----
    {
        float acc[4][4];
        gemm_mma(ahl_ad, reinterpret_cast<const uint4*>(g_bw), mt, ng, lane, acc);
        store_tile(RC, b_enc, mt, ng, lane, acc);
    }
    __syncthreads();
    {
        const float4* rc4 = reinterpret_cast<const float4*>(RC);
        float4 gm = *reinterpret_cast<const float4*>(g_enc + 4 * lane);
        float4 bt = *reinterpret_cast<const float4*>(beta_enc + 4 * lane);
        int t0 = wid * 4;
#pragma unroll
        for (int t = 0; t < 4; ++t) {
            float4 x = rc4[(t0 + t) * 33 + lane];
            float4 y = ln_warp(x, gm, bt);
            y = make_float4(fmaxf(y.x, 0.f), fmaxf(y.y, 0.f), fmaxf(y.z, 0.f), fmaxf(y.w, 0.f));
            hs4[(t0 + t) * 32 + lane] = y;
            store_ahl(ahl, t0 + t, lane, y);
        }
    }
    __syncthreads();

    // ---- Phase 3: transformer layers (fully HMMA) ----
    for (int d = 0; d < 3; ++d) {
        {
            const uint4* base = reinterpret_cast<const uint4*>(g_bw);
            float acc[4][4];
            gemm_mma(ahl_ad, base + (size_t)(3 + 3 * d) * 4096, mt, ng, lane, acc);
            store_vt(VT, bv + d * H_, mt, ng, lane, acc);           // V^T planes (direct)
            gemm_mma(ahl_ad, base + (size_t)(1 + 3 * d) * 4096, mt, ng, lane, acc);
            store_planes(QP, bq + d * H_, mt, ng, lane, acc);       // Q planes
            gemm_mma(ahl_ad, base + (size_t)(2 + 3 * d) * 4096, mt, ng, lane, acc);
            store_planes(KP, bk + d * H_, mt, ng, lane, acc);       // K planes
        }
        __syncthreads();

        attn_scores_softmax(qp_ad, kp_ad, KP, sval, pmax, psum, wid, lane);  // P overlays K planes
        __syncthreads();

        attn_ctx(kp_ad, vt_ad, RC, wid, lane);
        __syncthreads();

        {   // residual + LN epilogue (warp-local)
            const float4* rc4 = reinterpret_cast<const float4*>(RC);
            float4 gm = *reinterpret_cast<const float4*>(ln_g + d * H_ + 4 * lane);
            float4 bt = *reinterpret_cast<const float4*>(ln_b + d * H_ + 4 * lane);
            int t0 = wid * 4;
#pragma unroll
            for (int t = 0; t < 4; ++t) {
                int row = t0 + t;
                float4 cv = rc4[row * 33 + lane];
                float4 hv = hs4[row * 32 + lane];
                float4 x = make_float4(fmaxf(cv.x, 0.f) + hv.x, fmaxf(cv.y, 0.f) + hv.y,
                                       fmaxf(cv.z, 0.f) + hv.z, fmaxf(cv.w, 0.f) + hv.w);
                float4 y = ln_warp(x, gm, bt);
                hs4[row * 32 + lane] = y;
                if (d < 2) store_ahl(ahl, row, lane, y);
            }
        }
        __syncthreads();
    }

    // ---- Phase 4: max over T (scratch = RC) ----
    {
        const int part = tid >> 7;
        const int hh   = tid & 127;
        float m = -3.4e38f;
#pragma unroll
        for (int t = 0; t < 16; ++t)
            m = fmaxf(m, hs[(part * 16 + t) * H_ + hh]);
        RC[part * H_ + hh] = m;
    }
    __syncthreads();
    if (tid < H_)
        out[(size_t)blk * H_ + tid] = fmaxf(fmaxf(RC[tid], RC[H_ + tid]),
                                            fmaxf(RC[2 * H_ + tid], RC[3 * H_ + tid]));
}

} // namespace

extern "C" void kernel_launch(void* const* d_in, const int* in_sizes, int n_in,
                              void* d_out, int out_size) {
    const float* feat     = (const float*)d_in[0];
    const float* masks    = (const float*)d_in[1];
    const float* W_emb    = (const float*)d_in[2];
    const float* b_emb    = (const float*)d_in[3];
    const float* g_emb    = (const float*)d_in[4];
    const float* beta_emb = (const float*)d_in[5];
    const float* W_enc    = (const float*)d_in[6];
    const float* b_enc    = (const float*)d_in[7];
    const float* g_enc    = (const float*)d_in[8];
    const float* beta_enc = (const float*)d_in[9];
    const float* Wq       = (const float*)d_in[10];
    const float* bq       = (const float*)d_in[11];
    const float* Wk       = (const float*)d_in[12];
    const float* bk       = (const float*)d_in[13];
    const float* Wv       = (const float*)d_in[14];
    const float* bv       = (const float*)d_in[15];
    const float* ln_g     = (const float*)d_in[16];
    const float* ln_b     = (const float*)d_in[17];
    float* out = (float*)d_out;

    int nseq = in_sizes[0] / (64 * IN_);   // 4096
    pack_all<<<(1024 + BW_U32 + 255) / 256, 256>>>(W_emb, W_enc, Wq, Wk, Wv);

    size_t smem = (size_t)SM_FLOATS * 4;   // ~212KB
    cudaFuncSetAttribute(fused_lane_encoder,
                         cudaFuncAttributeMaxDynamicSharedMemorySize, (int)smem);
    fused_lane_encoder<<<nseq, NT, smem>>>(
        feat, masks, b_emb, g_emb, beta_emb, b_enc, g_enc, beta_enc,
        bq, bk, bv, ln_g, ln_b, out);
}